// round 7
// baseline (speedup 1.0000x reference)
#include <cuda_runtime.h>
#include <math.h>

#define NUM_NODES 17185
#define D 6
#define FEATS (NUM_NODES * D)   // 103110
#define BATCH 256
#define NPB 32                  // node lanes per block (= warp width)
#define GROUPS 16               // warps per block; warp g owns b = bi*16+g
#define ITERS 16                // batch rows per thread
#define PF 4                    // prefetch chunk (iterations batched per load burst)
#define NBLK ((NUM_NODES + NPB - 1) / NPB)  // 538
#define EPS 1e-5f

// Partials laid out [blk][b] so the last block's reduction reads coalesced.
__device__ float g_partial[NBLK * BATCH];
__device__ unsigned int g_ctr = 0;   // self-resetting arrival counter

__global__ void dummy_kernel() {}    // shifts ncu -s 5 -c 1 onto the fused kernel

__global__ __launch_bounds__(512, 1)
void fused_kernel(const float* __restrict__ data,
                  const float* __restrict__ w_blocks,
                  const float* __restrict__ b_blocks,
                  const float* __restrict__ bn_gamma,
                  const float* __restrict__ bn_beta,
                  const float* __restrict__ bn_mean,
                  const float* __restrict__ bn_var,
                  const float* __restrict__ fc_w,
                  const float* __restrict__ fc_b,
                  const float* __restrict__ bnf_gamma,
                  const float* __restrict__ bnf_beta,
                  const float* __restrict__ bnf_mean,
                  const float* __restrict__ bnf_var,
                  float* __restrict__ out)
{
    const int tid   = threadIdx.x;
    const int lane  = tid & 31;        // node lane within warp
    const int group = tid >> 5;        // warp id = batch group 0..15
    const int node  = blockIdx.x * NPB + lane;
    const bool valid = (node < NUM_NODES);

    // Per-thread node state, loaded ONCE, reused for 16 batch rows.
    float W[36];
    float bias[D], A[D];
    float CN = 0.0f;

    if (valid) {
        const float4* wp = reinterpret_cast<const float4*>(w_blocks + (size_t)node * 36);
        #pragma unroll
        for (int i = 0; i < 9; ++i) {
            float4 v = __ldg(&wp[i]);
            W[i*4+0] = v.x; W[i*4+1] = v.y; W[i*4+2] = v.z; W[i*4+3] = v.w;
        }
        const int f0 = node * D;
        #pragma unroll
        for (int o = 0; o < D; ++o) {
            const int f = f0 + o;
            bias[o] = b_blocks[f];
            const float rs = rsqrtf(bn_var[f] + EPS);
            const float g  = bn_gamma[f] * rs;
            const float fw = fc_w[f];
            A[o]  = g * fw;
            CN   += (bn_beta[f] - bn_mean[f] * g) * fw;
        }
    }

    // Hot loop: 4 chunks x 4 iterations. Each chunk front-batches 12
    // independent LDG.64s (MLP ~12/warp -> enough bytes in flight to
    // saturate HBM), then computes. All indices compile-time constants.
    float vacc[ITERS];
    const float* p0 = data + (size_t)node * D + (size_t)group * FEATS;
    const size_t step = (size_t)GROUPS * FEATS;   // b += 16 per iteration

    #pragma unroll
    for (int c = 0; c < ITERS / PF; ++c) {
        float2 buf[PF][3];
        #pragma unroll
        for (int j = 0; j < PF; ++j) {
            if (valid) {
                const float2* xp = reinterpret_cast<const float2*>(
                    p0 + (size_t)(c * PF + j) * step);
                buf[j][0] = __ldcs(&xp[0]);
                buf[j][1] = __ldcs(&xp[1]);
                buf[j][2] = __ldcs(&xp[2]);
            } else {
                buf[j][0] = buf[j][1] = buf[j][2] = make_float2(0.f, 0.f);
            }
        }
        #pragma unroll
        for (int j = 0; j < PF; ++j) {
            const float x[D] = {buf[j][0].x, buf[j][0].y,
                                buf[j][1].x, buf[j][1].y,
                                buf[j][2].x, buf[j][2].y};
            float acc = CN;
            #pragma unroll
            for (int o = 0; o < D; ++o) {
                float s = bias[o];
                #pragma unroll
                for (int i = 0; i < D; ++i)
                    s = fmaf(x[i], W[o * D + i], s);
                s = fmaxf(s, 0.0f);        // ReLU
                acc = fmaf(s, A[o], acc);  // folded BN * fc_w
            }
            vacc[c * PF + j] = valid ? acc : 0.0f;
        }
    }

    // One-shot epilogue: 16 butterflies across the 32 node lanes (fixed
    // order -> deterministic). Lane bi keeps the sum for b = bi*16+group.
    float keep = 0.0f;
    #pragma unroll
    for (int bi = 0; bi < ITERS; ++bi) {
        float a = vacc[bi];
        #pragma unroll
        for (int off = 16; off > 0; off >>= 1)
            a += __shfl_xor_sync(0xffffffffu, a, off);
        if (lane == bi) keep = a;
    }
    if (lane < ITERS) {
        const int b = lane * GROUPS + group;
        g_partial[blockIdx.x * BATCH + b] = keep;
    }

    // ---- last-block finalize (deterministic fixed-order reduction) ----
    __threadfence();          // each thread: publish its partials
    __syncthreads();
    __shared__ unsigned int s_last;
    if (tid == 0) {
        unsigned int old = atomicAdd(&g_ctr, 1u);
        s_last = (old == NBLK - 1) ? 1u : 0u;
        if (s_last) atomicExch(&g_ctr, 0u);   // reset for next launch
    }
    __syncthreads();
    if (!s_last) return;
    __threadfence();          // acquire side

    if (tid < BATCH) {
        const int b = tid;
        // 4 fixed-grouping accumulators: deterministic order, MLP=4.
        float s0 = 0.f, s1 = 0.f, s2 = 0.f, s3 = 0.f;
        int k = 0;
        #pragma unroll 2
        for (; k + 4 <= NBLK; k += 4) {           // 538 = 4*134 + 2
            s0 += g_partial[(k + 0) * BATCH + b]; // coalesced across b
            s1 += g_partial[(k + 1) * BATCH + b];
            s2 += g_partial[(k + 2) * BATCH + b];
            s3 += g_partial[(k + 3) * BATCH + b];
        }
        for (; k < NBLK; ++k) s0 += g_partial[k * BATCH + b];
        float t = ((s0 + s1) + (s2 + s3)) + fc_b[0];
        const float rs = rsqrtf(bnf_var[0] + EPS);
        const float y  = (t - bnf_mean[0]) * rs * bnf_gamma[0] + bnf_beta[0];
        out[b] = 1.0f / (1.0f + expf(-y));
    }
}

extern "C" void kernel_launch(void* const* d_in, const int* in_sizes, int n_in,
                              void* d_out, int out_size) {
    const float* data      = (const float*)d_in[0];
    const float* w_blocks  = (const float*)d_in[1];
    const float* b_blocks  = (const float*)d_in[2];
    const float* bn_gamma  = (const float*)d_in[3];
    const float* bn_beta   = (const float*)d_in[4];
    const float* bn_mean   = (const float*)d_in[5];
    const float* bn_var    = (const float*)d_in[6];
    const float* fc_w      = (const float*)d_in[7];
    const float* fc_b      = (const float*)d_in[8];
    const float* bnf_gamma = (const float*)d_in[9];
    const float* bnf_beta  = (const float*)d_in[10];
    const float* bnf_mean  = (const float*)d_in[11];
    const float* bnf_var   = (const float*)d_in[12];
    float* out = (float*)d_out;

    // Two no-op launches so ncu (-s 5 -c 1, i.e. launch #6 of a 3-kernel
    // replay) captures the FUSED kernel instead of a tail kernel.
    dummy_kernel<<<1, 32>>>();
    dummy_kernel<<<1, 32>>>();
    fused_kernel<<<NBLK, 512>>>(data, w_blocks, b_blocks, bn_gamma, bn_beta,
                                bn_mean, bn_var, fc_w, fc_b, bnf_gamma,
                                bnf_beta, bnf_mean, bnf_var, out);
}

// round 9
// speedup vs baseline: 1.3902x; 1.3902x over previous
#include <cuda_runtime.h>
#include <math.h>

#define NUM_NODES 17185
#define D 6
#define FEATS (NUM_NODES * D)   // 103110
#define BATCH 256
#define NPB 32                  // node lanes per block (= warp width)
#define GROUPS 16               // warps per block; warp g owns b = bi*16+g
#define ITERS 16                // batch rows per thread (fully unrolled)
#define NBLK ((NUM_NODES + NPB - 1) / NPB)  // 538
#define EPS 1e-5f

#define WPAD 37                 // padded smem row (gcd(37,32)=1 -> conflict-free)

// Partials [blk][b]; tail reads k-major, coalesced across b.
__device__ float g_partial[NBLK * BATCH];
__device__ unsigned int g_ctr = 0;   // self-resetting arrival counter

__global__ __launch_bounds__(512, 1)
void fused_kernel(const float* __restrict__ data,
                  const float* __restrict__ w_blocks,
                  const float* __restrict__ b_blocks,
                  const float* __restrict__ bn_gamma,
                  const float* __restrict__ bn_beta,
                  const float* __restrict__ bn_mean,
                  const float* __restrict__ bn_var,
                  const float* __restrict__ fc_w,
                  const float* __restrict__ fc_b,
                  const float* __restrict__ bnf_gamma,
                  const float* __restrict__ bnf_beta,
                  const float* __restrict__ bnf_mean,
                  const float* __restrict__ bnf_var,
                  float* __restrict__ out)
{
    __shared__ float sW[NPB * WPAD];      // 32 x 37 floats, padded
    __shared__ float sP[6][NPB * D];      // b, gamma, beta, mean, var, fc_w
    __shared__ float sh_tail[2][BATCH];
    __shared__ unsigned int s_last;

    const int tid   = threadIdx.x;
    const int lane  = tid & 31;        // node lane within warp
    const int group = tid >> 5;        // warp id = batch group 0..15
    const int node0 = blockIdx.x * NPB;
    const int node  = node0 + lane;
    const bool valid = (node < NUM_NODES);

    // ---- COALESCED prologue: contiguous GMEM -> SMEM staging ----
    // Weights: 32*36 = 1152 consecutive floats (vs per-thread 144B-stride gather).
    {
        const float* wsrc = w_blocks + (size_t)node0 * 36;
        const int wlim = NUM_NODES * 36 - node0 * 36;
        #pragma unroll
        for (int i = tid; i < NPB * 36; i += 512)
            sW[(i / 36) * WPAD + (i % 36)] = (i < wlim) ? wsrc[i] : 0.0f;

        const int plim = FEATS - node0 * D;
        #pragma unroll
        for (int i = tid; i < 6 * NPB * D; i += 512) {
            const int a = i / (NPB * D);
            const int j = i % (NPB * D);
            const float* src = (a == 0) ? b_blocks : (a == 1) ? bn_gamma :
                               (a == 2) ? bn_beta  : (a == 3) ? bn_mean  :
                               (a == 4) ? bn_var   : fc_w;
            sP[a][j] = (j < plim) ? src[(size_t)node0 * D + j] : 0.0f;
        }
    }
    __syncthreads();

    // Gather per-thread node state from SMEM (conflict-free thanks to WPAD=37).
    float W[36], bias[D], A[D];
    float CN = 0.0f;
    {
        const float* wrow = &sW[lane * WPAD];
        #pragma unroll
        for (int k = 0; k < 36; ++k) W[k] = wrow[k];
        #pragma unroll
        for (int o = 0; o < D; ++o) {
            const int j = lane * D + o;
            bias[o] = sP[0][j];
            const float rs = rsqrtf(sP[4][j] + EPS);
            const float g  = sP[1][j] * rs;
            const float fw = sP[5][j];
            A[o]  = g * fw;
            CN   += (sP[2][j] - sP[3][j] * g) * fw;
        }
    }

    // ---- Hot loop: R5's register loop, fully unrolled, no prefetch bufs ----
    float vacc[ITERS];
    const float* p = data + (size_t)node * D + (size_t)group * FEATS;

    #pragma unroll
    for (int bi = 0; bi < ITERS; ++bi) {
        float acc = 0.0f;
        if (valid) {
            const float2* xp = reinterpret_cast<const float2*>(p);
            const float2 x01 = __ldcs(&xp[0]);   // streaming read-once data
            const float2 x23 = __ldcs(&xp[1]);
            const float2 x45 = __ldcs(&xp[2]);
            const float x[D] = {x01.x, x01.y, x23.x, x23.y, x45.x, x45.y};
            acc = CN;
            #pragma unroll
            for (int o = 0; o < D; ++o) {
                float s = bias[o];
                #pragma unroll
                for (int i = 0; i < D; ++i)
                    s = fmaf(x[i], W[o * D + i], s);
                s = fmaxf(s, 0.0f);        // ReLU
                acc = fmaf(s, A[o], acc);  // folded BN * fc_w
            }
        }
        vacc[bi] = acc;                    // constant index -> register
        p += (size_t)GROUPS * FEATS;       // b += 16
    }

    // One-shot butterflies across node lanes (fixed order -> deterministic).
    float keep = 0.0f;
    #pragma unroll
    for (int bi = 0; bi < ITERS; ++bi) {
        float a = vacc[bi];
        #pragma unroll
        for (int off = 16; off > 0; off >>= 1)
            a += __shfl_xor_sync(0xffffffffu, a, off);
        if (lane == bi) keep = a;
    }
    if (lane < ITERS)
        g_partial[blockIdx.x * BATCH + (lane * GROUPS + group)] = keep;

    // ---- last-block tail (deterministic fixed-order reduction) ----
    __threadfence();                      // publish partials (all threads)
    __syncthreads();
    if (tid == 0) {
        const unsigned int old = atomicAdd(&g_ctr, 1u);
        s_last = (old == (unsigned)(NBLK - 1)) ? 1u : 0u;
        if (s_last) atomicExch(&g_ctr, 0u);   // reset for next launch
    }
    __syncthreads();
    if (!s_last) return;
    __threadfence();                      // acquire

    {
        const int b    = tid & 255;
        const int half = tid >> 8;        // 0/1 -> k-halves
        const int k0   = half * 269;      // 538 = 2 * 269
        float s0 = 0.f, s1 = 0.f, s2 = 0.f, s3 = 0.f;
        int j = 0;
        for (; j + 4 <= 269; j += 4) {    // fixed grouping, MLP=4, coalesced
            s0 += g_partial[(k0 + j + 0) * BATCH + b];
            s1 += g_partial[(k0 + j + 1) * BATCH + b];
            s2 += g_partial[(k0 + j + 2) * BATCH + b];
            s3 += g_partial[(k0 + j + 3) * BATCH + b];
        }
        for (; j < 269; ++j) s0 += g_partial[(k0 + j) * BATCH + b];
        sh_tail[half][b] = ((s0 + s1) + (s2 + s3));
    }
    __syncthreads();
    if (tid < BATCH) {
        const float t  = sh_tail[0][tid] + sh_tail[1][tid] + fc_b[0];
        const float rs = rsqrtf(bnf_var[0] + EPS);
        const float y  = (t - bnf_mean[0]) * rs * bnf_gamma[0] + bnf_beta[0];
        out[tid] = 1.0f / (1.0f + expf(-y));
    }
}

extern "C" void kernel_launch(void* const* d_in, const int* in_sizes, int n_in,
                              void* d_out, int out_size) {
    const float* data      = (const float*)d_in[0];
    const float* w_blocks  = (const float*)d_in[1];
    const float* b_blocks  = (const float*)d_in[2];
    const float* bn_gamma  = (const float*)d_in[3];
    const float* bn_beta   = (const float*)d_in[4];
    const float* bn_mean   = (const float*)d_in[5];
    const float* bn_var    = (const float*)d_in[6];
    const float* fc_w      = (const float*)d_in[7];
    const float* fc_b      = (const float*)d_in[8];
    const float* bnf_gamma = (const float*)d_in[9];
    const float* bnf_beta  = (const float*)d_in[10];
    const float* bnf_mean  = (const float*)d_in[11];
    const float* bnf_var   = (const float*)d_in[12];
    float* out = (float*)d_out;

    fused_kernel<<<NBLK, 512>>>(data, w_blocks, b_blocks, bn_gamma, bn_beta,
                                bn_mean, bn_var, fc_w, fc_b, bnf_gamma,
                                bnf_beta, bnf_mean, bnf_var, out);
}

// round 11
// speedup vs baseline: 1.5054x; 1.0828x over previous
#include <cuda_runtime.h>
#include <math.h>
#include <stdint.h>

#define NUM_NODES 17185
#define D 6
#define FEATS (NUM_NODES * D)   // 103110
#define BATCH 256
#define NPB 32                  // node lanes per block (= warp width)
#define GROUPS 16               // warps; warp g owns batch rows b = bi*16+g
#define ITERS 16                // batch rows per thread
#define NBLK ((NUM_NODES + NPB - 1) / NPB)  // 538
#define EPS 1e-5f

#define STAGES 3
#define ROWF (NPB * D)          // 192 floats per staged row slice
#define ROWF2 (ROWF / 2)        // 96 float2
#define STAGE_F2 (GROUPS * ROWF2)  // 1536 float2 per stage (exactly 3/thread)
#define WPAD 37

// Partials [blk][b]; tail reads coalesced across b.
__device__ float g_partial[NBLK * BATCH];
__device__ unsigned int g_ctr = 0;

__device__ __forceinline__ void cp_async8(uint32_t dst, const float* src, int src_bytes) {
    asm volatile("cp.async.ca.shared.global [%0], [%1], 8, %2;\n"
                 :: "r"(dst), "l"(src), "r"(src_bytes));
}
__device__ __forceinline__ void cp_commit() {
    asm volatile("cp.async.commit_group;\n" ::: "memory");
}
__device__ __forceinline__ void cp_wait2() {
    asm volatile("cp.async.wait_group 2;\n" ::: "memory");
}

__global__ __launch_bounds__(512, 1)
void fused_kernel(const float* __restrict__ data,
                  const float* __restrict__ w_blocks,
                  const float* __restrict__ b_blocks,
                  const float* __restrict__ bn_gamma,
                  const float* __restrict__ bn_beta,
                  const float* __restrict__ bn_mean,
                  const float* __restrict__ bn_var,
                  const float* __restrict__ fc_w,
                  const float* __restrict__ fc_b,
                  const float* __restrict__ bnf_gamma,
                  const float* __restrict__ bnf_beta,
                  const float* __restrict__ bnf_mean,
                  const float* __restrict__ bnf_var,
                  float* __restrict__ out)
{
    __shared__ float sData[STAGES][GROUPS][ROWF];   // 36 KB ring buffer
    __shared__ float sW[NPB * WPAD];                // 4.7 KB staged weights
    __shared__ float sh_tail[2][BATCH];
    __shared__ unsigned int s_last;

    const int tid   = threadIdx.x;
    const int lane  = tid & 31;
    const int group = tid >> 5;
    const int node0 = blockIdx.x * NPB;
    const int node  = node0 + lane;
    const bool valid = (node < NUM_NODES);

    const size_t rowbase = (size_t)node0 * D;       // float offset within a row
    const size_t total_f = (size_t)BATCH * FEATS;

    // --- stage loader: 1536 float2 cp.asyncs, fully coalesced, zfill OOB ---
    auto load_stage = [&](int bi) {
        const int s = bi % STAGES;
        #pragma unroll
        for (int k = 0; k < 3; ++k) {               // 3 * 512 = 1536
            const int idx = tid + k * 512;
            const int row = idx / ROWF2;
            const int v   = idx % ROWF2;
            const size_t fofs = (size_t)(bi * GROUPS + row) * FEATS + rowbase + v * 2;
            const int ok = (fofs + 2 <= total_f) ? 8 : 0;   // last-row tail guard
            uint32_t dst = (uint32_t)__cvta_generic_to_shared(&sData[s][row][v * 2]);
            cp_async8(dst, data + fofs, ok);
        }
    };

    // Prologue: get 2 stages in flight BEFORE touching weights (overlap).
    load_stage(0); cp_commit();
    load_stage(1); cp_commit();

    // Coalesced weight staging (kills the 144B-stride gather wavefront storm).
    {
        const float* wsrc = w_blocks + (size_t)node0 * 36;
        const int wlim = NUM_NODES * 36 - node0 * 36;
        #pragma unroll
        for (int i = tid; i < NPB * 36; i += 512)
            sW[(i / 36) * WPAD + (i % 36)] = (i < wlim) ? wsrc[i] : 0.0f;
    }
    __syncthreads();

    float W[36], bias[D], A[D];
    float CN = 0.0f;
    {
        const float* wrow = &sW[lane * WPAD];
        #pragma unroll
        for (int k = 0; k < 36; ++k) W[k] = wrow[k];
        const int f0 = node * D;
        #pragma unroll
        for (int o = 0; o < D; ++o) {
            const int f = valid ? (f0 + o) : 0;
            bias[o] = b_blocks[f];
            const float rs = rsqrtf(bn_var[f] + EPS);
            const float g  = bn_gamma[f] * rs;
            const float fw = fc_w[f];
            A[o]  = g * fw;
            CN   += (bn_beta[f] - bn_mean[f] * g) * fw;
        }
    }

    // --- pipelined hot loop: cp.async keeps 24KB/SM in flight ---
    float vacc[ITERS];
    #pragma unroll
    for (int bi = 0; bi < ITERS; ++bi) {
        if (bi + 2 < ITERS) load_stage(bi + 2);
        cp_commit();
        cp_wait2();            // stage bi complete
        __syncthreads();       // visible to all warps

        const float* rp = &sData[bi % STAGES][group][lane * D];
        const float2 x01 = *reinterpret_cast<const float2*>(rp + 0);
        const float2 x23 = *reinterpret_cast<const float2*>(rp + 2);
        const float2 x45 = *reinterpret_cast<const float2*>(rp + 4);
        const float x[D] = {x01.x, x01.y, x23.x, x23.y, x45.x, x45.y};
        float acc = CN;
        #pragma unroll
        for (int o = 0; o < D; ++o) {
            float s = bias[o];
            #pragma unroll
            for (int i = 0; i < D; ++i)
                s = fmaf(x[i], W[o * D + i], s);
            s = fmaxf(s, 0.0f);
            acc = fmaf(s, A[o], acc);
        }
        vacc[bi] = valid ? acc : 0.0f;

        __syncthreads();       // all reads done before buffer is overwritten
    }

    // One-shot butterflies across node lanes (fixed order -> deterministic).
    float keep = 0.0f;
    #pragma unroll
    for (int bi = 0; bi < ITERS; ++bi) {
        float a = vacc[bi];
        #pragma unroll
        for (int off = 16; off > 0; off >>= 1)
            a += __shfl_xor_sync(0xffffffffu, a, off);
        if (lane == bi) keep = a;
    }
    if (lane < ITERS)
        g_partial[blockIdx.x * BATCH + (lane * GROUPS + group)] = keep;

    // --- last-block tail (deterministic fixed-order reduction) ---
    __threadfence();
    __syncthreads();
    if (tid == 0) {
        const unsigned int old = atomicAdd(&g_ctr, 1u);
        s_last = (old == (unsigned)(NBLK - 1)) ? 1u : 0u;
        if (s_last) atomicExch(&g_ctr, 0u);
    }
    __syncthreads();
    if (!s_last) return;
    __threadfence();

    {
        const int b    = tid & 255;
        const int half = tid >> 8;        // 538 = 2 * 269
        const int k0   = half * 269;
        float s0 = 0.f, s1 = 0.f, s2 = 0.f, s3 = 0.f;
        int j = 0;
        for (; j + 4 <= 269; j += 4) {
            s0 += g_partial[(k0 + j + 0) * BATCH + b];
            s1 += g_partial[(k0 + j + 1) * BATCH + b];
            s2 += g_partial[(k0 + j + 2) * BATCH + b];
            s3 += g_partial[(k0 + j + 3) * BATCH + b];
        }
        for (; j < 269; ++j) s0 += g_partial[(k0 + j) * BATCH + b];
        sh_tail[half][b] = ((s0 + s1) + (s2 + s3));
    }
    __syncthreads();
    if (tid < BATCH) {
        const float t  = sh_tail[0][tid] + sh_tail[1][tid] + fc_b[0];
        const float rs = rsqrtf(bnf_var[0] + EPS);
        const float y  = (t - bnf_mean[0]) * rs * bnf_gamma[0] + bnf_beta[0];
        out[tid] = 1.0f / (1.0f + expf(-y));
    }
}

extern "C" void kernel_launch(void* const* d_in, const int* in_sizes, int n_in,
                              void* d_out, int out_size) {
    const float* data      = (const float*)d_in[0];
    const float* w_blocks  = (const float*)d_in[1];
    const float* b_blocks  = (const float*)d_in[2];
    const float* bn_gamma  = (const float*)d_in[3];
    const float* bn_beta   = (const float*)d_in[4];
    const float* bn_mean   = (const float*)d_in[5];
    const float* bn_var    = (const float*)d_in[6];
    const float* fc_w      = (const float*)d_in[7];
    const float* fc_b      = (const float*)d_in[8];
    const float* bnf_gamma = (const float*)d_in[9];
    const float* bnf_beta  = (const float*)d_in[10];
    const float* bnf_mean  = (const float*)d_in[11];
    const float* bnf_var   = (const float*)d_in[12];
    float* out = (float*)d_out;

    fused_kernel<<<NBLK, 512>>>(data, w_blocks, b_blocks, bn_gamma, bn_beta,
                                bn_mean, bn_var, fc_w, fc_b, bnf_gamma,
                                bnf_beta, bnf_mean, bnf_var, out);
}